// round 11
// baseline (speedup 1.0000x reference)
#include <cuda_runtime.h>
#include <cstdint>
#include <cstddef>

#define N_NODES 50000
#define N_EDGES 800000
#define N_LINE  800000
#define D 128
#define NL 3

// ---------------- scratch (static device globals; no allocations) ----------------
__device__ float g_nf0[(size_t)N_NODES * D];
__device__ float g_nf1[(size_t)N_NODES * D];
__device__ float g_ef0[(size_t)N_EDGES * D];
__device__ float g_ef1[(size_t)N_EDGES * D];
__device__ unsigned int g_pool[2 * D];
__device__ uint32_t g_wpk[20 * 16384];
// CSR structures (rebuilt every call; indices are static inputs)
__device__ int g_c1o[N_NODES + 1], g_c1c[N_NODES], g_c1l[N_EDGES];  // an:  nf[ei0]->ei1
__device__ int g_c2o[N_NODES + 1], g_c2c[N_NODES], g_c2l[N_EDGES];  // a1n: ef[nei]->nes
__device__ int g_c3o[N_EDGES + 1], g_c3c[N_EDGES], g_c3l[N_LINE];   // ae:  ef[lei0]->lei1
__device__ int g_c4o[N_EDGES + 1], g_c4c[N_EDGES], g_c4l[N_LINE];   // a1e: nf[eni]->ens
__device__ int g_bs[4][1024];

// ============================ CSR build kernels ==================================
__global__ void hist_k(const int* __restrict__ dst, int* __restrict__ cnt, int n)
{
    int i = blockIdx.x * blockDim.x + threadIdx.x;
    if (i < n) atomicAdd(&cnt[dst[i]], 1);
}

#define SCAN_B 1024
// in-place block-local exclusive scan (1024 elems / block, 256 threads x 4)
__global__ void scan1_k(int* __restrict__ data, int* __restrict__ bsums, int n)
{
    __shared__ int sh[256];
    int t = threadIdx.x;
    int idx = blockIdx.x * SCAN_B + t * 4;
    int v[4], s = 0;
#pragma unroll
    for (int k = 0; k < 4; k++) { v[k] = (idx + k < n) ? data[idx + k] : 0; s += v[k]; }
    sh[t] = s;
    __syncthreads();
#pragma unroll
    for (int o = 1; o < 256; o <<= 1) {
        int x = (t >= o) ? sh[t - o] : 0;
        __syncthreads();
        sh[t] += x;
        __syncthreads();
    }
    int run = sh[t] - s;
#pragma unroll
    for (int k = 0; k < 4; k++) { if (idx + k < n) data[idx + k] = run; run += v[k]; }
    if (t == 255) bsums[blockIdx.x] = sh[255];
}

__global__ void scan2_k(int* __restrict__ bsums, int nb)  // single block, exclusive
{
    __shared__ int sh[1024];
    int t = threadIdx.x;
    int v = (t < nb) ? bsums[t] : 0;
    sh[t] = v;
    __syncthreads();
#pragma unroll
    for (int o = 1; o < 1024; o <<= 1) {
        int x = (t >= o) ? sh[t - o] : 0;
        __syncthreads();
        sh[t] += x;
        __syncthreads();
    }
    if (t < nb) bsums[t] = sh[t] - v;
}

__global__ void scan3_k(int* __restrict__ data, const int* __restrict__ bsums,
                        int* __restrict__ cur, int n)
{
    int i = blockIdx.x * blockDim.x + threadIdx.x;
    if (i < n) {
        int v = data[i] + bsums[i / SCAN_B];
        data[i] = v;
        if (i < n - 1) cur[i] = v;
    }
}

__global__ void fill_k(const int* __restrict__ src, const int* __restrict__ dst,
                       int* __restrict__ cur, int* __restrict__ list, int n)
{
    int i = blockIdx.x * blockDim.x + threadIdx.x;
    if (i < n) {
        int p = atomicAdd(&cur[dst[i]], 1);
        list[p] = src[i];
    }
}

// ============================ bf16 split helpers =================================
__device__ __forceinline__ uint32_t packbf(float hi_el, float lo_el) {
    uint32_t r;
    asm("cvt.rn.bf16x2.f32 %0, %1, %2;" : "=r"(r) : "f"(hi_el), "f"(lo_el));
    return r;
}
__device__ __forceinline__ float bf_lo(uint32_t u) { return __uint_as_float(u << 16); }
__device__ __forceinline__ float bf_hi(uint32_t u) { return __uint_as_float(u & 0xFFFF0000u); }

__device__ __forceinline__ void mma16(float* d, uint32_t a0, uint32_t a1, uint32_t a2,
                                      uint32_t a3, uint32_t b0, uint32_t b1)
{
    asm volatile(
        "mma.sync.aligned.m16n8k16.row.col.f32.bf16.bf16.f32 "
        "{%0,%1,%2,%3}, {%4,%5,%6,%7}, {%8,%9}, {%0,%1,%2,%3};"
        : "+f"(d[0]), "+f"(d[1]), "+f"(d[2]), "+f"(d[3])
        : "r"(a0), "r"(a1), "r"(a2), "r"(a3), "r"(b0), "r"(b1));
}

__device__ __forceinline__ void ldm4(uint32_t* r, uint32_t addr) {
    asm volatile("ldmatrix.sync.aligned.m8n8.x4.shared.b16 {%0,%1,%2,%3}, [%4];"
                 : "=r"(r[0]), "=r"(r[1]), "=r"(r[2]), "=r"(r[3]) : "r"(addr));
}
__device__ __forceinline__ void cp16(uint32_t dst, const void* src) {
    asm volatile("cp.async.ca.shared.global [%0], [%1], 16;" :: "r"(dst), "l"(src));
}
#define CP_COMMIT() asm volatile("cp.async.commit_group;" ::: "memory")
#define CP_WAIT0()  asm volatile("cp.async.wait_group 0;" ::: "memory")

// ---------------- weight pre-pack (single launch, all 20 matrices) ---------------
__global__ void wprep_all_k(const float* __restrict__ nWc, const float* __restrict__ nWn,
                            const float* __restrict__ nWe, const float* __restrict__ eWc,
                            const float* __restrict__ eWn, const float* __restrict__ eWe,
                            const float* __restrict__ Wno, const float* __restrict__ Weo,
                            uint32_t* __restrict__ out)
{
    int i = blockIdx.x * blockDim.x + threadIdx.x;
    if (i >= 20 * 8192) return;
    int m = i >> 13, r = i & 8191;
    int n = r >> 6, k2 = r & 63;
    const float* srcs[8] = { nWc, nWn, nWe, eWc, eWn, eWe, Wno, Weo };
    int grp = (m < 18) ? (m / 3) : (m - 18 + 6);
    int loc = (m < 18) ? (m % 3) : 0;
    const float* w = srcs[grp] + (size_t)loc * 16384;
    float x0 = w[(2 * k2) * D + n];
    float x1 = w[(2 * k2 + 1) * D + n];
    uint32_t hi = packbf(x1, x0);
    float r0 = x0 - bf_lo(hi);
    float r1 = x1 - bf_hi(hi);
    uint32_t lo = packbf(r1, r0);
    out[(size_t)m * 16384 + n * 64 + k2]        = hi;
    out[(size_t)m * 16384 + 8192 + n * 64 + k2] = lo;
}

// SMEM (dynamic, 82944 B): bias | inv | two 40960B stages | epilogue staging aliased
#define SM_TOTAL 82944
#define STG_BYTES 40960

// ---- fused A-row source: sel 0 = direct x0; sel 1/2 = CSR gather-sum ------------
__device__ __forceinline__ void load_av(
    float4* av, const float* __restrict__ x0,
    const float* __restrict__ f1, const int* __restrict__ o1, const int* __restrict__ l1,
    const float* __restrict__ f2, const int* __restrict__ o2, const int* __restrict__ l2,
    int sel, int row0, int M, int kofs, int ar, int aj)
{
#pragma unroll
    for (int h = 0; h < 4; h++) {
        int r = row0 + ar + h * 32;
        float4 s = make_float4(0.f, 0.f, 0.f, 0.f);
        if (r < M) {
            if (sel == 0) {
                s = *(const float4*)(x0 + (size_t)r * D + kofs + aj * 4);
            } else {
                const float* f  = (sel == 1) ? f1 : f2;
                const int* off  = (sel == 1) ? o1 : o2;
                const int* lst  = (sel == 1) ? l1 : l2;
                int a = off[r], b = off[r + 1];
                for (int k = a; k < b; k++) {
                    float4 v = *(const float4*)(f + (size_t)lst[k] * D + kofs + aj * 4);
                    s.x += v.x; s.y += v.y; s.z += v.z; s.w += v.w;
                }
            }
        }
        av[h] = s;
    }
}

// ========== bf16x3 tensor-core GEMM with fused CSR aggregation ===================
__global__ void __launch_bounds__(256, 2) tc_gemm_k(
    const float* __restrict__ x0,
    const float* __restrict__ f1, const int* __restrict__ o1, const int* __restrict__ l1,
    const float* __restrict__ f2, const int* __restrict__ o2, const int* __restrict__ l2,
    const uint32_t* __restrict__ pk0, const uint32_t* __restrict__ pk1,
    const uint32_t* __restrict__ pk2,
    const float* __restrict__ b0, const float* __restrict__ b1, const float* __restrict__ b2,
    float* __restrict__ out, int M, int nsrc, int donorm, int act,
    unsigned int* __restrict__ pool)
{
    extern __shared__ char smem[];
    float* bias_s = (float*)smem;
    float* inv_s  = (float*)(smem + 512);
    uint32_t stiles = (uint32_t)__cvta_generic_to_shared(smem) + 1024;

    int t = threadIdx.x;
    int lane = t & 31, wid = t >> 5;
    int warpm = wid >> 2, warpn = wid & 3;
    int gid = lane >> 2, tig = lane & 3;
    int row0 = blockIdx.x * 128;

    if (t < D) {
        float bb = b0[t];
        if (nsrc == 3) bb += b1[t] + b2[t];
        bias_s[t] = bb;
    }

    int arow = warpm * 64 + (lane & 7) + ((lane >> 3) & 1) * 8;
    uint32_t aoff = (uint32_t)(arow * 80) + (lane >> 4) * 16;
    int nrow = warpn * 32 + (lane & 7) + (lane >> 4) * 8;
    uint32_t boff = (uint32_t)(nrow * 80) + ((lane >> 3) & 1) * 16;

    int ar = t >> 3;
    int aj = t & 7;

    float acc[4][4][4];
#pragma unroll
    for (int i = 0; i < 4; i++)
#pragma unroll
        for (int j = 0; j < 4; j++)
#pragma unroll
            for (int k = 0; k < 4; k++) acc[i][j][k] = 0.f;

    const uint32_t* ps[3] = { pk0, pk1, pk2 };
    const int nch = nsrc * 4;

    float4 av[4];

    // ---- prologue: chunk 0 into stage 0 ----------------------------------------
    {
        load_av(av, x0, f1, o1, l1, f2, o2, l2, 0, row0, M, 0, ar, aj);
        const uint32_t* sH = ps[0];
        const uint32_t* sL = ps[0] + 8192;
        uint32_t dH = stiles + 20480, dL = stiles + 30720;
#pragma unroll
        for (int i = 0; i < 2; i++) {
            int idx = t + i * 256;
            int n = idx >> 2, j4 = idx & 3;
            cp16(dH + n * 80 + j4 * 16, sH + n * 64 + j4 * 4);
            cp16(dL + n * 80 + j4 * 16, sL + n * 64 + j4 * 4);
        }
        CP_COMMIT();
        uint32_t* pH = (uint32_t*)(smem + 1024);
        uint32_t* pL = (uint32_t*)(smem + 1024 + 10240);
#pragma unroll
        for (int h = 0; h < 4; h++) {
            int r = ar + h * 32;
            float4 v = av[h];
            uint32_t h0 = packbf(v.y, v.x), h1 = packbf(v.w, v.z);
            float r0 = v.x - bf_lo(h0), r1 = v.y - bf_hi(h0);
            float r2 = v.z - bf_lo(h1), r3 = v.w - bf_hi(h1);
            *(uint2*)(pH + r * 20 + aj * 2) = make_uint2(h0, h1);
            *(uint2*)(pL + r * 20 + aj * 2) = make_uint2(packbf(r1, r0), packbf(r3, r2));
        }
        CP_WAIT0();
    }
    __syncthreads();

    // ---- main pipelined loop ----------------------------------------------------
    for (int c = 0; c < nch; c++) {
        int s = c & 1;
        int have_next = (c + 1 < nch);

        if (have_next) {
            int c1 = c + 1;
            load_av(av, x0, f1, o1, l1, f2, o2, l2, c1 >> 2, row0, M, (c1 & 3) * 32, ar, aj);
            const uint32_t* pk = ps[c1 >> 2];
            int k2o = (c1 & 3) * 16;
            const uint32_t* sH = pk + k2o;
            const uint32_t* sL = pk + 8192 + k2o;
            uint32_t sb = stiles + (s ^ 1) * STG_BYTES;
            uint32_t dH = sb + 20480, dL = sb + 30720;
#pragma unroll
            for (int i = 0; i < 2; i++) {
                int idx = t + i * 256;
                int n = idx >> 2, j4 = idx & 3;
                cp16(dH + n * 80 + j4 * 16, sH + n * 64 + j4 * 4);
                cp16(dL + n * 80 + j4 * 16, sL + n * 64 + j4 * 4);
            }
            CP_COMMIT();
        }

        // ---- MMA on stage s via ldmatrix ----------------------------------------
        {
            uint32_t bAH = stiles + s * STG_BYTES;
            uint32_t bAL = bAH + 10240;
            uint32_t bBH = bAH + 20480;
            uint32_t bBL = bAH + 30720;
#pragma unroll
            for (int ks = 0; ks < 2; ks++) {
                uint32_t kso = ks * 32;
                uint32_t bh[4][2], bl[4][2], r4[4];
#pragma unroll
                for (int p = 0; p < 2; p++) {
                    ldm4(r4, bBH + boff + p * 1280 + kso);
                    bh[2 * p][0] = r4[0]; bh[2 * p][1] = r4[1];
                    bh[2 * p + 1][0] = r4[2]; bh[2 * p + 1][1] = r4[3];
                    ldm4(r4, bBL + boff + p * 1280 + kso);
                    bl[2 * p][0] = r4[0]; bl[2 * p][1] = r4[1];
                    bl[2 * p + 1][0] = r4[2]; bl[2 * p + 1][1] = r4[3];
                }
#pragma unroll
                for (int mf = 0; mf < 4; mf++) {
                    uint32_t ah[4], al[4];
                    ldm4(ah, bAH + aoff + mf * 1280 + kso);
                    ldm4(al, bAL + aoff + mf * 1280 + kso);
#pragma unroll
                    for (int nf = 0; nf < 4; nf++) {
                        mma16(acc[mf][nf], ah[0], ah[1], ah[2], ah[3], bh[nf][0], bh[nf][1]);
                        mma16(acc[mf][nf], ah[0], ah[1], ah[2], ah[3], bl[nf][0], bl[nf][1]);
                        mma16(acc[mf][nf], al[0], al[1], al[2], al[3], bh[nf][0], bh[nf][1]);
                    }
                }
            }
        }

        if (have_next) {
            uint32_t* pH = (uint32_t*)(smem + 1024 + (s ^ 1) * STG_BYTES);
            uint32_t* pL = pH + 2560;
#pragma unroll
            for (int h = 0; h < 4; h++) {
                int r = ar + h * 32;
                float4 v = av[h];
                uint32_t h0 = packbf(v.y, v.x), h1 = packbf(v.w, v.z);
                float r0 = v.x - bf_lo(h0), r1 = v.y - bf_hi(h0);
                float r2 = v.z - bf_lo(h1), r3 = v.w - bf_hi(h1);
                *(uint2*)(pH + r * 20 + aj * 2) = make_uint2(h0, h1);
                *(uint2*)(pL + r * 20 + aj * 2) = make_uint2(packbf(r1, r0), packbf(r3, r2));
            }
            CP_WAIT0();
        }
        __syncthreads();
    }

    // ---- epilogue: stage acc + bias into smem (aliases operand tiles) ----------
    float* stg = (float*)(smem + 1024);                // 128 x 132 floats
#pragma unroll
    for (int mf = 0; mf < 4; mf++) {
        int row = warpm * 64 + mf * 16 + gid;
#pragma unroll
        for (int nf = 0; nf < 4; nf++) {
            int col = warpn * 32 + nf * 8 + 2 * tig;
            stg[row * 132 + col]           = acc[mf][nf][0] + bias_s[col];
            stg[row * 132 + col + 1]       = acc[mf][nf][1] + bias_s[col + 1];
            stg[(row + 8) * 132 + col]     = acc[mf][nf][2] + bias_s[col];
            stg[(row + 8) * 132 + col + 1] = acc[mf][nf][3] + bias_s[col + 1];
        }
    }
    __syncthreads();

    if (donorm && t < 128) {
        float ssq = 0.f;
#pragma unroll
        for (int j = 0; j < 32; j++) {
            float4 v = *(float4*)(stg + t * 132 + j * 4);
            ssq += v.x * v.x + v.y * v.y + v.z * v.z + v.w * v.w;
        }
        inv_s[t] = 1.0f / fmaxf(sqrtf(ssq), 1e-12f);
    }
    __syncthreads();

    int sl = t & 31;
    float4 pmax = make_float4(-3.402823466e38f, -3.402823466e38f,
                              -3.402823466e38f, -3.402823466e38f);
#pragma unroll
    for (int h = 0; h < 16; h++) {
        int idx = t + h * 256;
        int row = idx >> 5;
        float4 v = *(float4*)(stg + row * 132 + sl * 4);
        if (donorm) {
            float iv = inv_s[row];
            v.x *= iv; v.y *= iv; v.z *= iv; v.w *= iv;
            if (act) {
                v.x = (v.x >= 0.f) ? v.x : 0.01f * v.x;
                v.y = (v.y >= 0.f) ? v.y : 0.01f * v.y;
                v.z = (v.z >= 0.f) ? v.z : 0.01f * v.z;
                v.w = (v.w >= 0.f) ? v.w : 0.01f * v.w;
            }
        }
        if (row0 + row < M) {
            *(float4*)(out + (size_t)(row0 + row) * D + sl * 4) = v;
            if (pool) {
                pmax.x = fmaxf(pmax.x, v.x); pmax.y = fmaxf(pmax.y, v.y);
                pmax.z = fmaxf(pmax.z, v.z); pmax.w = fmaxf(pmax.w, v.w);
            }
        }
    }
    if (pool) {
        float pv[4] = { pmax.x, pmax.y, pmax.z, pmax.w };
#pragma unroll
        for (int j = 0; j < 4; j++) {
            unsigned u = __float_as_uint(pv[j]);
            unsigned mono = (u & 0x80000000u) ? ~u : (u | 0x80000000u);
            atomicMax(&pool[sl * 4 + j], mono);
        }
    }
}

__global__ void pool_combine_k(unsigned int* __restrict__ pool, float* __restrict__ out)
{
    int t = threadIdx.x;  // 128
    unsigned a = pool[t], bmono = pool[t + D];
    float fa = __uint_as_float((a & 0x80000000u) ? (a & 0x7fffffffu) : ~a);
    float fb = __uint_as_float((bmono & 0x80000000u) ? (bmono & 0x7fffffffu) : ~bmono);
    out[t] = fa + fb;
    pool[t] = 0u;
    pool[t + D] = 0u;
}

// --------- one-time stream/event setup (first, uncaptured, call) -----------------
struct AsyncCtx {
    cudaStream_t s1;
    cudaEvent_t evF, evW, evJ, evGN[NL], evGE[NL];
    AsyncCtx() {
        cudaStreamCreateWithFlags(&s1, cudaStreamNonBlocking);
        cudaEventCreateWithFlags(&evF, cudaEventDisableTiming);
        cudaEventCreateWithFlags(&evW, cudaEventDisableTiming);
        cudaEventCreateWithFlags(&evJ, cudaEventDisableTiming);
        for (int i = 0; i < NL; i++) {
            cudaEventCreateWithFlags(&evGN[i], cudaEventDisableTiming);
            cudaEventCreateWithFlags(&evGE[i], cudaEventDisableTiming);
        }
    }
};

static void build_csr(const int* src, const int* dst, int cnt_n,
                      int* off, int* cur, int* list, int m, int* bs, cudaStream_t st)
{
    int nscan = m + 1;
    int nb = (nscan + SCAN_B - 1) / SCAN_B;
    cudaMemsetAsync(off, 0, (size_t)nscan * sizeof(int), st);
    hist_k<<<(cnt_n + 255) / 256, 256, 0, st>>>(dst, off, cnt_n);
    scan1_k<<<nb, 256, 0, st>>>(off, bs, nscan);
    scan2_k<<<1, 1024, 0, st>>>(bs, nb);
    scan3_k<<<(nscan + 255) / 256, 256, 0, st>>>(off, bs, cur, nscan);
    fill_k<<<(cnt_n + 255) / 256, 256, 0, st>>>(src, dst, cur, list, cnt_n);
}

// ---------------------------------- launch ---------------------------------------
extern "C" void kernel_launch(void* const* d_in, const int* in_sizes, int n_in,
                              void* d_out, int out_size)
{
    static AsyncCtx ax;

    const float* nf_in = (const float*)d_in[0];
    const float* ef_in = (const float*)d_in[1];
    const float* nWc = (const float*)d_in[2];
    const float* nbc = (const float*)d_in[3];
    const float* nWn = (const float*)d_in[4];
    const float* nbn = (const float*)d_in[5];
    const float* nWe = (const float*)d_in[6];
    const float* nbe = (const float*)d_in[7];
    const float* eWc = (const float*)d_in[8];
    const float* ebc = (const float*)d_in[9];
    const float* eWn = (const float*)d_in[10];
    const float* ebn = (const float*)d_in[11];
    const float* eWe = (const float*)d_in[12];
    const float* ebe = (const float*)d_in[13];
    const float* Wno = (const float*)d_in[14];
    const float* bno = (const float*)d_in[15];
    const float* Weo = (const float*)d_in[16];
    const float* beo = (const float*)d_in[17];
    const int* ei  = (const int*)d_in[18];   // [2, E]
    const int* lei = (const int*)d_in[19];   // [2, L]
    const int* nei = (const int*)d_in[20];   // [E]
    const int* nes = (const int*)d_in[21];   // [E]
    const int* eni = (const int*)d_in[22];   // [L]
    const int* ens = (const int*)d_in[23];   // [L]
    float* outp = (float*)d_out;             // [pooled(128) | tn(N*128) | te(E*128)]

    cudaFuncSetAttribute(tc_gemm_k, cudaFuncAttributeMaxDynamicSharedMemorySize, SM_TOTAL);

    float *nf0, *nf1, *ef0, *ef1;
    unsigned int* pool;
    uint32_t* wpk;
    int *c1o, *c1c, *c1l, *c2o, *c2c, *c2l, *c3o, *c3c, *c3l, *c4o, *c4c, *c4l, *bs;
    cudaGetSymbolAddress((void**)&nf0, g_nf0);
    cudaGetSymbolAddress((void**)&nf1, g_nf1);
    cudaGetSymbolAddress((void**)&ef0, g_ef0);
    cudaGetSymbolAddress((void**)&ef1, g_ef1);
    cudaGetSymbolAddress((void**)&pool, g_pool);
    cudaGetSymbolAddress((void**)&wpk, g_wpk);
    cudaGetSymbolAddress((void**)&c1o, g_c1o); cudaGetSymbolAddress((void**)&c1c, g_c1c);
    cudaGetSymbolAddress((void**)&c1l, g_c1l);
    cudaGetSymbolAddress((void**)&c2o, g_c2o); cudaGetSymbolAddress((void**)&c2c, g_c2c);
    cudaGetSymbolAddress((void**)&c2l, g_c2l);
    cudaGetSymbolAddress((void**)&c3o, g_c3o); cudaGetSymbolAddress((void**)&c3c, g_c3c);
    cudaGetSymbolAddress((void**)&c3l, g_c3l);
    cudaGetSymbolAddress((void**)&c4o, g_c4o); cudaGetSymbolAddress((void**)&c4c, g_c4c);
    cudaGetSymbolAddress((void**)&c4l, g_c4l);
    cudaGetSymbolAddress((void**)&bs, g_bs);

    cudaStream_t s0 = 0, s1 = ax.s1;

    // fork s1
    cudaEventRecord(ax.evF, s0);
    cudaStreamWaitEvent(s1, ax.evF, 0);

    // s0: weights + node CSRs.  s1: edge CSRs (concurrent).
    wprep_all_k<<<(20 * 8192 + 255) / 256, 256, 0, s0>>>(nWc, nWn, nWe, eWc, eWn, eWe,
                                                         Wno, Weo, wpk);
    cudaEventRecord(ax.evW, s0);
    build_csr(ei,  ei + N_EDGES, N_EDGES, c1o, c1c, c1l, N_NODES, bs,            s0);
    build_csr(nei, nes,          N_EDGES, c2o, c2c, c2l, N_NODES, bs + 1024,     s0);
    build_csr(lei, lei + N_LINE, N_LINE,  c3o, c3c, c3l, N_EDGES, bs + 2048,     s1);
    build_csr(eni, ens,          N_LINE,  c4o, c4c, c4l, N_EDGES, bs + 3072,     s1);
    cudaStreamWaitEvent(s1, ax.evW, 0);   // G_edge(0) needs packed weights

    float* nf_bufs[2] = { nf0, nf1 };
    float* ef_bufs[2] = { ef0, ef1 };
    const float* nf_cur = nf_in;
    const float* ef_cur = ef_in;

    const int NGB = (N_NODES + 127) / 128;   // 391
    const int EGB = (N_EDGES + 127) / 128;   // 6250

    for (int i = 0; i < NL; i++) {
        float* nf_next = nf_bufs[i & 1];
        float* ef_next = ef_bufs[i & 1];
        int act = (i < NL - 1);

        // G_node(i) on s0: x0=nf, agg1=CSR1(nf), agg2=CSR2(ef)
        if (i > 0) cudaStreamWaitEvent(s0, ax.evGE[i - 1], 0);   // ef(i-1) RAW (+WAR)
        tc_gemm_k<<<NGB, 256, SM_TOTAL, s0>>>(
            nf_cur, nf_cur, c1o, c1l, ef_cur, c2o, c2l,
            wpk + (size_t)(0 + i) * 16384, wpk + (size_t)(3 + i) * 16384,
            wpk + (size_t)(6 + i) * 16384,
            nbc + i * D, nbn + i * D, nbe + i * D,
            nf_next, N_NODES, 3, 1, act, nullptr);
        cudaEventRecord(ax.evGN[i], s0);

        // G_edge(i) on s1: x0=ef, agg1=CSR3(ef), agg2=CSR4(nf_old)
        if (i > 0) cudaStreamWaitEvent(s1, ax.evGN[i - 1], 0);   // nf(i-1) RAW (+WAR)
        tc_gemm_k<<<EGB, 256, SM_TOTAL, s1>>>(
            ef_cur, ef_cur, c3o, c3l, nf_cur, c4o, c4l,
            wpk + (size_t)(9 + i) * 16384, wpk + (size_t)(12 + i) * 16384,
            wpk + (size_t)(15 + i) * 16384,
            ebc + i * D, ebn + i * D, ebe + i * D,
            ef_next, N_EDGES, 3, 1, act, nullptr);
        cudaEventRecord(ax.evGE[i], s1);

        nf_cur = nf_next;
        ef_cur = ef_next;
    }

    // output linears + fused max-pool (concurrent)
    tc_gemm_k<<<NGB, 256, SM_TOTAL, s0>>>(
        nf_cur, nullptr, nullptr, nullptr, nullptr, nullptr, nullptr,
        wpk + (size_t)18 * 16384, nullptr, nullptr,
        bno, nullptr, nullptr,
        outp + D, N_NODES, 1, 0, 0, pool);
    tc_gemm_k<<<EGB, 256, SM_TOTAL, s1>>>(
        ef_cur, nullptr, nullptr, nullptr, nullptr, nullptr, nullptr,
        wpk + (size_t)19 * 16384, nullptr, nullptr,
        beo, nullptr, nullptr,
        outp + D + (size_t)N_NODES * D, N_EDGES, 1, 0, 0, pool + D);
    cudaEventRecord(ax.evJ, s1);
    cudaStreamWaitEvent(s0, ax.evJ, 0);

    pool_combine_k<<<1, 128, 0, s0>>>(pool, outp);
}

// round 13
// speedup vs baseline: 1.2692x; 1.2692x over previous
#include <cuda_runtime.h>
#include <cstdint>
#include <cstddef>

#define N_NODES 50000
#define N_EDGES 800000
#define N_LINE  800000
#define D 128
#define NL 3

// ---------------- scratch (static device globals; no allocations) ----------------
__device__ float g_nf0[(size_t)N_NODES * D];
__device__ float g_nf1[(size_t)N_NODES * D];
__device__ float g_ef0[(size_t)N_EDGES * D];
__device__ float g_ef1[(size_t)N_EDGES * D];
__device__ float g_an [(size_t)N_NODES * D];
__device__ float g_a1n[(size_t)N_NODES * D];
__device__ float g_ae [(size_t)N_EDGES * D];
__device__ float g_a1e0[(size_t)N_EDGES * D];  // ping-pong (cross-stream WAR)
__device__ float g_a1e1[(size_t)N_EDGES * D];
__device__ unsigned int g_pool[2 * D];
__device__ uint32_t g_wpk[20 * 16384];
// CSR structures (rebuilt every call; indices are static inputs)
__device__ int g_c1o[N_NODES + 1], g_c1c[N_NODES], g_c1l[N_EDGES];  // an:  nf[ei0]->ei1
__device__ int g_c2o[N_NODES + 1], g_c2c[N_NODES], g_c2l[N_EDGES];  // a1n: ef[nei]->nes
__device__ int g_c3o[N_EDGES + 1], g_c3c[N_EDGES], g_c3l[N_LINE];   // ae:  ef[lei0]->lei1
__device__ int g_c4o[N_EDGES + 1], g_c4c[N_EDGES], g_c4l[N_LINE];   // a1e: nf[eni]->ens
__device__ int g_bs[4][1024];

// ============================ CSR build kernels ==================================
__global__ void hist_k(const int* __restrict__ dst, int* __restrict__ cnt, int n)
{
    int i = blockIdx.x * blockDim.x + threadIdx.x;
    if (i < n) atomicAdd(&cnt[dst[i]], 1);
}

#define SCAN_B 1024
__global__ void scan1_k(int* __restrict__ data, int* __restrict__ bsums, int n)
{
    __shared__ int sh[256];
    int t = threadIdx.x;
    int idx = blockIdx.x * SCAN_B + t * 4;
    int v[4], s = 0;
#pragma unroll
    for (int k = 0; k < 4; k++) { v[k] = (idx + k < n) ? data[idx + k] : 0; s += v[k]; }
    sh[t] = s;
    __syncthreads();
#pragma unroll
    for (int o = 1; o < 256; o <<= 1) {
        int x = (t >= o) ? sh[t - o] : 0;
        __syncthreads();
        sh[t] += x;
        __syncthreads();
    }
    int run = sh[t] - s;
#pragma unroll
    for (int k = 0; k < 4; k++) { if (idx + k < n) data[idx + k] = run; run += v[k]; }
    if (t == 255) bsums[blockIdx.x] = sh[255];
}

__global__ void scan2_k(int* __restrict__ bsums, int nb)
{
    __shared__ int sh[1024];
    int t = threadIdx.x;
    int v = (t < nb) ? bsums[t] : 0;
    sh[t] = v;
    __syncthreads();
#pragma unroll
    for (int o = 1; o < 1024; o <<= 1) {
        int x = (t >= o) ? sh[t - o] : 0;
        __syncthreads();
        sh[t] += x;
        __syncthreads();
    }
    if (t < nb) bsums[t] = sh[t] - v;
}

__global__ void scan3_k(int* __restrict__ data, const int* __restrict__ bsums,
                        int* __restrict__ cur, int n)
{
    int i = blockIdx.x * blockDim.x + threadIdx.x;
    if (i < n) {
        int v = data[i] + bsums[i / SCAN_B];
        data[i] = v;
        if (i < n - 1) cur[i] = v;
    }
}

__global__ void fill_k(const int* __restrict__ src, const int* __restrict__ dst,
                       int* __restrict__ cur, int* __restrict__ list, int n)
{
    int i = blockIdx.x * blockDim.x + threadIdx.x;
    if (i < n) {
        int p = atomicAdd(&cur[dst[i]], 1);
        list[p] = src[i];
    }
}

// ---------------- destination-major gather-sum (replaces scatter_add) ------------
__global__ void gather_sum_k(const float* __restrict__ src, float* __restrict__ dst,
                             const int* __restrict__ off, const int* __restrict__ lst,
                             int m)
{
    int lane  = threadIdx.x & 31;
    int warp  = (blockIdx.x * blockDim.x + threadIdx.x) >> 5;
    int nwarp = (gridDim.x * blockDim.x) >> 5;
    for (int r = warp; r < m; r += nwarp) {
        int a = off[r], b = off[r + 1];
        float4 acc = make_float4(0.f, 0.f, 0.f, 0.f);
        int k = a;
        for (; k + 1 < b; k += 2) {
            int g0 = lst[k], g1 = lst[k + 1];
            float4 v0 = *((const float4*)(src + (size_t)g0 * D) + lane);
            float4 v1 = *((const float4*)(src + (size_t)g1 * D) + lane);
            acc.x += v0.x + v1.x; acc.y += v0.y + v1.y;
            acc.z += v0.z + v1.z; acc.w += v0.w + v1.w;
        }
        if (k < b) {
            float4 v = *((const float4*)(src + (size_t)lst[k] * D) + lane);
            acc.x += v.x; acc.y += v.y; acc.z += v.z; acc.w += v.w;
        }
        *((float4*)(dst + (size_t)r * D) + lane) = acc;
    }
}

// ============================ bf16 split helpers =================================
__device__ __forceinline__ uint32_t packbf(float hi_el, float lo_el) {
    uint32_t r;
    asm("cvt.rn.bf16x2.f32 %0, %1, %2;" : "=r"(r) : "f"(hi_el), "f"(lo_el));
    return r;
}
__device__ __forceinline__ float bf_lo(uint32_t u) { return __uint_as_float(u << 16); }
__device__ __forceinline__ float bf_hi(uint32_t u) { return __uint_as_float(u & 0xFFFF0000u); }

__device__ __forceinline__ void mma16(float* d, uint32_t a0, uint32_t a1, uint32_t a2,
                                      uint32_t a3, uint32_t b0, uint32_t b1)
{
    asm volatile(
        "mma.sync.aligned.m16n8k16.row.col.f32.bf16.bf16.f32 "
        "{%0,%1,%2,%3}, {%4,%5,%6,%7}, {%8,%9}, {%0,%1,%2,%3};"
        : "+f"(d[0]), "+f"(d[1]), "+f"(d[2]), "+f"(d[3])
        : "r"(a0), "r"(a1), "r"(a2), "r"(a3), "r"(b0), "r"(b1));
}

__device__ __forceinline__ void ldm4(uint32_t* r, uint32_t addr) {
    asm volatile("ldmatrix.sync.aligned.m8n8.x4.shared.b16 {%0,%1,%2,%3}, [%4];"
                 : "=r"(r[0]), "=r"(r[1]), "=r"(r[2]), "=r"(r[3]) : "r"(addr));
}
__device__ __forceinline__ void cp16(uint32_t dst, const void* src) {
    asm volatile("cp.async.ca.shared.global [%0], [%1], 16;" :: "r"(dst), "l"(src));
}
#define CP_COMMIT() asm volatile("cp.async.commit_group;" ::: "memory")
#define CP_WAIT0()  asm volatile("cp.async.wait_group 0;" ::: "memory")

// ---------------- weight pre-pack (single launch, all 20 matrices) ---------------
__global__ void wprep_all_k(const float* __restrict__ nWc, const float* __restrict__ nWn,
                            const float* __restrict__ nWe, const float* __restrict__ eWc,
                            const float* __restrict__ eWn, const float* __restrict__ eWe,
                            const float* __restrict__ Wno, const float* __restrict__ Weo,
                            uint32_t* __restrict__ out)
{
    int i = blockIdx.x * blockDim.x + threadIdx.x;
    if (i >= 20 * 8192) return;
    int m = i >> 13, r = i & 8191;
    int n = r >> 6, k2 = r & 63;
    const float* srcs[8] = { nWc, nWn, nWe, eWc, eWn, eWe, Wno, Weo };
    int grp = (m < 18) ? (m / 3) : (m - 18 + 6);
    int loc = (m < 18) ? (m % 3) : 0;
    const float* w = srcs[grp] + (size_t)loc * 16384;
    float x0 = w[(2 * k2) * D + n];
    float x1 = w[(2 * k2 + 1) * D + n];
    uint32_t hi = packbf(x1, x0);
    float r0 = x0 - bf_lo(hi);
    float r1 = x1 - bf_hi(hi);
    uint32_t lo = packbf(r1, r0);
    out[(size_t)m * 16384 + n * 64 + k2]        = hi;
    out[(size_t)m * 16384 + 8192 + n * 64 + k2] = lo;
}

// SMEM (dynamic, 82944 B): bias | inv | two 40960B stages | epilogue staging aliased
#define SM_TOTAL 82944
#define STG_BYTES 40960

// ========== bf16x3 tensor-core GEMM, cp.async + ldmatrix 2-stage pipeline ========
__global__ void __launch_bounds__(256, 2) tc_gemm_k(
    const float* __restrict__ x0, const float* __restrict__ x1, const float* __restrict__ x2,
    const uint32_t* __restrict__ pk0, const uint32_t* __restrict__ pk1,
    const uint32_t* __restrict__ pk2,
    const float* __restrict__ b0, const float* __restrict__ b1, const float* __restrict__ b2,
    float* __restrict__ out, int M, int nsrc, int donorm, int act,
    unsigned int* __restrict__ pool)
{
    extern __shared__ char smem[];
    float* bias_s = (float*)smem;
    float* inv_s  = (float*)(smem + 512);
    uint32_t stiles = (uint32_t)__cvta_generic_to_shared(smem) + 1024;

    int t = threadIdx.x;
    int lane = t & 31, wid = t >> 5;
    int warpm = wid >> 2, warpn = wid & 3;
    int gid = lane >> 2, tig = lane & 3;
    int row0 = blockIdx.x * 128;

    if (t < D) {
        float bb = b0[t];
        if (nsrc == 3) bb += b1[t] + b2[t];
        bias_s[t] = bb;
    }

    int arow = warpm * 64 + (lane & 7) + ((lane >> 3) & 1) * 8;
    uint32_t aoff = (uint32_t)(arow * 80) + (lane >> 4) * 16;
    int nrow = warpn * 32 + (lane & 7) + (lane >> 4) * 8;
    uint32_t boff = (uint32_t)(nrow * 80) + ((lane >> 3) & 1) * 16;

    int ar = t >> 3;
    int aj = t & 7;

    float acc[4][4][4];
#pragma unroll
    for (int i = 0; i < 4; i++)
#pragma unroll
        for (int j = 0; j < 4; j++)
#pragma unroll
            for (int k = 0; k < 4; k++) acc[i][j][k] = 0.f;

    const float* xs[3] = { x0, x1, x2 };
    const uint32_t* ps[3] = { pk0, pk1, pk2 };
    const int nch = nsrc * 4;

    float4 av[4];

    // ---- prologue: chunk 0 into stage 0 ----------------------------------------
    {
        const float* src = xs[0];
#pragma unroll
        for (int h = 0; h < 4; h++) {
            int r = ar + h * 32;
            av[h] = make_float4(0.f, 0.f, 0.f, 0.f);
            if (row0 + r < M)
                av[h] = *(const float4*)(src + (size_t)(row0 + r) * D + aj * 4);
        }
        const uint32_t* sH = ps[0];
        const uint32_t* sL = ps[0] + 8192;
        uint32_t dH = stiles + 20480, dL = stiles + 30720;
#pragma unroll
        for (int i = 0; i < 2; i++) {
            int idx = t + i * 256;
            int n = idx >> 2, j4 = idx & 3;
            cp16(dH + n * 80 + j4 * 16, sH + n * 64 + j4 * 4);
            cp16(dL + n * 80 + j4 * 16, sL + n * 64 + j4 * 4);
        }
        CP_COMMIT();
        uint32_t* pH = (uint32_t*)(smem + 1024);
        uint32_t* pL = (uint32_t*)(smem + 1024 + 10240);
#pragma unroll
        for (int h = 0; h < 4; h++) {
            int r = ar + h * 32;
            float4 v = av[h];
            uint32_t h0 = packbf(v.y, v.x), h1 = packbf(v.w, v.z);
            float r0 = v.x - bf_lo(h0), r1 = v.y - bf_hi(h0);
            float r2 = v.z - bf_lo(h1), r3 = v.w - bf_hi(h1);
            *(uint2*)(pH + r * 20 + aj * 2) = make_uint2(h0, h1);
            *(uint2*)(pL + r * 20 + aj * 2) = make_uint2(packbf(r1, r0), packbf(r3, r2));
        }
        CP_WAIT0();
    }
    __syncthreads();

    // ---- main pipelined loop ----------------------------------------------------
    for (int c = 0; c < nch; c++) {
        int s = c & 1;
        int have_next = (c + 1 < nch);

        if (have_next) {
            int c1 = c + 1;
            const float* src = xs[c1 >> 2];
            int kofs = (c1 & 3) * 32;
#pragma unroll
            for (int h = 0; h < 4; h++) {
                int r = ar + h * 32;
                av[h] = make_float4(0.f, 0.f, 0.f, 0.f);
                if (row0 + r < M)
                    av[h] = *(const float4*)(src + (size_t)(row0 + r) * D + kofs + aj * 4);
            }
            const uint32_t* pk = ps[c1 >> 2];
            int k2o = (c1 & 3) * 16;
            const uint32_t* sH = pk + k2o;
            const uint32_t* sL = pk + 8192 + k2o;
            uint32_t sb = stiles + (s ^ 1) * STG_BYTES;
            uint32_t dH = sb + 20480, dL = sb + 30720;
#pragma unroll
            for (int i = 0; i < 2; i++) {
                int idx = t + i * 256;
                int n = idx >> 2, j4 = idx & 3;
                cp16(dH + n * 80 + j4 * 16, sH + n * 64 + j4 * 4);
                cp16(dL + n * 80 + j4 * 16, sL + n * 64 + j4 * 4);
            }
            CP_COMMIT();
        }

        // ---- MMA on stage s via ldmatrix ----------------------------------------
        {
            uint32_t bAH = stiles + s * STG_BYTES;
            uint32_t bAL = bAH + 10240;
            uint32_t bBH = bAH + 20480;
            uint32_t bBL = bAH + 30720;
#pragma unroll
            for (int ks = 0; ks < 2; ks++) {
                uint32_t kso = ks * 32;
                uint32_t bh[4][2], bl[4][2], r4[4];
#pragma unroll
                for (int p = 0; p < 2; p++) {
                    ldm4(r4, bBH + boff + p * 1280 + kso);
                    bh[2 * p][0] = r4[0]; bh[2 * p][1] = r4[1];
                    bh[2 * p + 1][0] = r4[2]; bh[2 * p + 1][1] = r4[3];
                    ldm4(r4, bBL + boff + p * 1280 + kso);
                    bl[2 * p][0] = r4[0]; bl[2 * p][1] = r4[1];
                    bl[2 * p + 1][0] = r4[2]; bl[2 * p + 1][1] = r4[3];
                }
#pragma unroll
                for (int mf = 0; mf < 4; mf++) {
                    uint32_t ah[4], al[4];
                    ldm4(ah, bAH + aoff + mf * 1280 + kso);
                    ldm4(al, bAL + aoff + mf * 1280 + kso);
#pragma unroll
                    for (int nf = 0; nf < 4; nf++) {
                        mma16(acc[mf][nf], ah[0], ah[1], ah[2], ah[3], bh[nf][0], bh[nf][1]);
                        mma16(acc[mf][nf], ah[0], ah[1], ah[2], ah[3], bl[nf][0], bl[nf][1]);
                        mma16(acc[mf][nf], al[0], al[1], al[2], al[3], bh[nf][0], bh[nf][1]);
                    }
                }
            }
        }

        if (have_next) {
            uint32_t* pH = (uint32_t*)(smem + 1024 + (s ^ 1) * STG_BYTES);
            uint32_t* pL = pH + 2560;
#pragma unroll
            for (int h = 0; h < 4; h++) {
                int r = ar + h * 32;
                float4 v = av[h];
                uint32_t h0 = packbf(v.y, v.x), h1 = packbf(v.w, v.z);
                float r0 = v.x - bf_lo(h0), r1 = v.y - bf_hi(h0);
                float r2 = v.z - bf_lo(h1), r3 = v.w - bf_hi(h1);
                *(uint2*)(pH + r * 20 + aj * 2) = make_uint2(h0, h1);
                *(uint2*)(pL + r * 20 + aj * 2) = make_uint2(packbf(r1, r0), packbf(r3, r2));
            }
            CP_WAIT0();
        }
        __syncthreads();
    }

    // ---- epilogue: stage acc + bias into smem (aliases operand tiles) ----------
    float* stg = (float*)(smem + 1024);                // 128 x 132 floats
#pragma unroll
    for (int mf = 0; mf < 4; mf++) {
        int row = warpm * 64 + mf * 16 + gid;
#pragma unroll
        for (int nf = 0; nf < 4; nf++) {
            int col = warpn * 32 + nf * 8 + 2 * tig;
            stg[row * 132 + col]           = acc[mf][nf][0] + bias_s[col];
            stg[row * 132 + col + 1]       = acc[mf][nf][1] + bias_s[col + 1];
            stg[(row + 8) * 132 + col]     = acc[mf][nf][2] + bias_s[col];
            stg[(row + 8) * 132 + col + 1] = acc[mf][nf][3] + bias_s[col + 1];
        }
    }
    __syncthreads();

    if (donorm && t < 128) {
        float ssq = 0.f;
#pragma unroll
        for (int j = 0; j < 32; j++) {
            float4 v = *(float4*)(stg + t * 132 + j * 4);
            ssq += v.x * v.x + v.y * v.y + v.z * v.z + v.w * v.w;
        }
        inv_s[t] = 1.0f / fmaxf(sqrtf(ssq), 1e-12f);
    }
    __syncthreads();

    int sl = t & 31;
    float4 pmax = make_float4(-3.402823466e38f, -3.402823466e38f,
                              -3.402823466e38f, -3.402823466e38f);
#pragma unroll
    for (int h = 0; h < 16; h++) {
        int idx = t + h * 256;
        int row = idx >> 5;
        float4 v = *(float4*)(stg + row * 132 + sl * 4);
        if (donorm) {
            float iv = inv_s[row];
            v.x *= iv; v.y *= iv; v.z *= iv; v.w *= iv;
            if (act) {
                v.x = (v.x >= 0.f) ? v.x : 0.01f * v.x;
                v.y = (v.y >= 0.f) ? v.y : 0.01f * v.y;
                v.z = (v.z >= 0.f) ? v.z : 0.01f * v.z;
                v.w = (v.w >= 0.f) ? v.w : 0.01f * v.w;
            }
        }
        if (row0 + row < M) {
            *(float4*)(out + (size_t)(row0 + row) * D + sl * 4) = v;
            if (pool) {
                pmax.x = fmaxf(pmax.x, v.x); pmax.y = fmaxf(pmax.y, v.y);
                pmax.z = fmaxf(pmax.z, v.z); pmax.w = fmaxf(pmax.w, v.w);
            }
        }
    }
    if (pool) {
        float pv[4] = { pmax.x, pmax.y, pmax.z, pmax.w };
#pragma unroll
        for (int j = 0; j < 4; j++) {
            unsigned u = __float_as_uint(pv[j]);
            unsigned mono = (u & 0x80000000u) ? ~u : (u | 0x80000000u);
            atomicMax(&pool[sl * 4 + j], mono);
        }
    }
}

__global__ void pool_combine_k(unsigned int* __restrict__ pool, float* __restrict__ out)
{
    int t = threadIdx.x;  // 128
    unsigned a = pool[t], bmono = pool[t + D];
    float fa = __uint_as_float((a & 0x80000000u) ? (a & 0x7fffffffu) : ~a);
    float fb = __uint_as_float((bmono & 0x80000000u) ? (bmono & 0x7fffffffu) : ~bmono);
    out[t] = fa + fb;
    pool[t] = 0u;
    pool[t + D] = 0u;
}

// --------- one-time stream/event setup (first, uncaptured, call) -----------------
struct AsyncCtx {
    cudaStream_t s1;
    cudaEvent_t evF, evW, evC, evJ, evGN[NL], evGE[NL], evS4[NL];
    AsyncCtx() {
        cudaStreamCreateWithFlags(&s1, cudaStreamNonBlocking);
        cudaEventCreateWithFlags(&evF, cudaEventDisableTiming);
        cudaEventCreateWithFlags(&evW, cudaEventDisableTiming);
        cudaEventCreateWithFlags(&evC, cudaEventDisableTiming);
        cudaEventCreateWithFlags(&evJ, cudaEventDisableTiming);
        for (int i = 0; i < NL; i++) {
            cudaEventCreateWithFlags(&evGN[i], cudaEventDisableTiming);
            cudaEventCreateWithFlags(&evGE[i], cudaEventDisableTiming);
            cudaEventCreateWithFlags(&evS4[i], cudaEventDisableTiming);
        }
    }
};

static void build_csr(const int* src, const int* dst, int cnt_n,
                      int* off, int* cur, int* list, int m, int* bs, cudaStream_t st)
{
    int nscan = m + 1;
    int nb = (nscan + SCAN_B - 1) / SCAN_B;
    cudaMemsetAsync(off, 0, (size_t)nscan * sizeof(int), st);
    hist_k<<<(cnt_n + 255) / 256, 256, 0, st>>>(dst, off, cnt_n);
    scan1_k<<<nb, 256, 0, st>>>(off, bs, nscan);
    scan2_k<<<1, 1024, 0, st>>>(bs, nb);
    scan3_k<<<(nscan + 255) / 256, 256, 0, st>>>(off, bs, cur, nscan);
    fill_k<<<(cnt_n + 255) / 256, 256, 0, st>>>(src, dst, cur, list, cnt_n);
}

// ---------------------------------- launch ---------------------------------------
extern "C" void kernel_launch(void* const* d_in, const int* in_sizes, int n_in,
                              void* d_out, int out_size)
{
    static AsyncCtx ax;

    const float* nf_in = (const float*)d_in[0];
    const float* ef_in = (const float*)d_in[1];
    const float* nWc = (const float*)d_in[2];
    const float* nbc = (const float*)d_in[3];
    const float* nWn = (const float*)d_in[4];
    const float* nbn = (const float*)d_in[5];
    const float* nWe = (const float*)d_in[6];
    const float* nbe = (const float*)d_in[7];
    const float* eWc = (const float*)d_in[8];
    const float* ebc = (const float*)d_in[9];
    const float* eWn = (const float*)d_in[10];
    const float* ebn = (const float*)d_in[11];
    const float* eWe = (const float*)d_in[12];
    const float* ebe = (const float*)d_in[13];
    const float* Wno = (const float*)d_in[14];
    const float* bno = (const float*)d_in[15];
    const float* Weo = (const float*)d_in[16];
    const float* beo = (const float*)d_in[17];
    const int* ei  = (const int*)d_in[18];   // [2, E]
    const int* lei = (const int*)d_in[19];   // [2, L]
    const int* nei = (const int*)d_in[20];   // [E]
    const int* nes = (const int*)d_in[21];   // [E]
    const int* eni = (const int*)d_in[22];   // [L]
    const int* ens = (const int*)d_in[23];   // [L]
    float* outp = (float*)d_out;             // [pooled(128) | tn(N*128) | te(E*128)]

    cudaFuncSetAttribute(tc_gemm_k, cudaFuncAttributeMaxDynamicSharedMemorySize, SM_TOTAL);

    float *nf0, *nf1, *ef0, *ef1, *an, *a1n, *ae, *a1eP[2];
    unsigned int* pool;
    uint32_t* wpk;
    int *c1o, *c1c, *c1l, *c2o, *c2c, *c2l, *c3o, *c3c, *c3l, *c4o, *c4c, *c4l, *bs;
    cudaGetSymbolAddress((void**)&nf0, g_nf0);
    cudaGetSymbolAddress((void**)&nf1, g_nf1);
    cudaGetSymbolAddress((void**)&ef0, g_ef0);
    cudaGetSymbolAddress((void**)&ef1, g_ef1);
    cudaGetSymbolAddress((void**)&an,  g_an);
    cudaGetSymbolAddress((void**)&a1n, g_a1n);
    cudaGetSymbolAddress((void**)&ae,  g_ae);
    cudaGetSymbolAddress((void**)&a1eP[0], g_a1e0);
    cudaGetSymbolAddress((void**)&a1eP[1], g_a1e1);
    cudaGetSymbolAddress((void**)&pool, g_pool);
    cudaGetSymbolAddress((void**)&wpk, g_wpk);
    cudaGetSymbolAddress((void**)&c1o, g_c1o); cudaGetSymbolAddress((void**)&c1c, g_c1c);
    cudaGetSymbolAddress((void**)&c1l, g_c1l);
    cudaGetSymbolAddress((void**)&c2o, g_c2o); cudaGetSymbolAddress((void**)&c2c, g_c2c);
    cudaGetSymbolAddress((void**)&c2l, g_c2l);
    cudaGetSymbolAddress((void**)&c3o, g_c3o); cudaGetSymbolAddress((void**)&c3c, g_c3c);
    cudaGetSymbolAddress((void**)&c3l, g_c3l);
    cudaGetSymbolAddress((void**)&c4o, g_c4o); cudaGetSymbolAddress((void**)&c4c, g_c4c);
    cudaGetSymbolAddress((void**)&c4l, g_c4l);
    cudaGetSymbolAddress((void**)&bs, g_bs);

    cudaStream_t s0 = 0, s1 = ax.s1;

    // fork s1
    cudaEventRecord(ax.evF, s0);
    cudaStreamWaitEvent(s1, ax.evF, 0);

    // s0: weights + node CSRs.  s1: edge CSRs (concurrent).
    wprep_all_k<<<(20 * 8192 + 255) / 256, 256, 0, s0>>>(nWc, nWn, nWe, eWc, eWn, eWe,
                                                         Wno, Weo, wpk);
    cudaEventRecord(ax.evW, s0);
    build_csr(ei,  ei + N_EDGES, N_EDGES, c1o, c1c, c1l, N_NODES, bs,        s0);
    build_csr(nei, nes,          N_EDGES, c2o, c2c, c2l, N_NODES, bs + 1024, s0);
    build_csr(lei, lei + N_LINE, N_LINE,  c3o, c3c, c3l, N_EDGES, bs + 2048, s1);
    build_csr(eni, ens,          N_LINE,  c4o, c4c, c4l, N_EDGES, bs + 3072, s1);
    cudaEventRecord(ax.evC, s1);          // s1 CSR builds complete (c3, c4)
    cudaStreamWaitEvent(s1, ax.evW, 0);   // G_edge(0) needs packed weights
    cudaStreamWaitEvent(s0, ax.evC, 0);   // *** FIX: s0's a1e gather reads c4 ***

    float* nf_bufs[2] = { nf0, nf1 };
    float* ef_bufs[2] = { ef0, ef1 };
    const float* nf_cur = nf_in;
    const float* ef_cur = ef_in;

    const int EGW = 25000;    // gather grid (edge-sized outputs)
    const int NGW = 6250;     // gather grid (node-sized outputs)
    const int NGB = (N_NODES + 127) / 128;   // 391
    const int EGB = (N_EDGES + 127) / 128;   // 6250

    for (int i = 0; i < NL; i++) {
        float* nf_next = nf_bufs[i & 1];
        float* ef_next = ef_bufs[i & 1];
        float* a1e = a1eP[i & 1];
        int act = (i < NL - 1);

        // ---- s0: nf-sourced gathers (run during previous G_edge) ---------------
        // WAR on a1e[p]: previous reader is G_edge(i-2); s0 waited evGE[i-2] in
        // layer i-1, ordering these writes. nf_cur is s0-local.
        gather_sum_k<<<NGW, 256, 0, s0>>>(nf_cur, an,  c1o, c1l, N_NODES);
        gather_sum_k<<<EGW, 256, 0, s0>>>(nf_cur, a1e, c4o, c4l, N_EDGES);
        cudaEventRecord(ax.evS4[i], s0);

        // ---- ef-sourced gathers (need ef_cur = G_edge(i-1) output) -------------
        if (i > 0) cudaStreamWaitEvent(s0, ax.evGE[i - 1], 0);
        gather_sum_k<<<EGW, 256, 0, s0>>>(ef_cur, a1n, c2o, c2l, N_NODES);
        gather_sum_k<<<EGW, 256, 0, s1>>>(ef_cur, ae,  c3o, c3l, N_EDGES);

        // G_node(i) on s0
        tc_gemm_k<<<NGB, 256, SM_TOTAL, s0>>>(nf_cur, an, a1n,
                                              wpk + (size_t)(0 + i) * 16384,
                                              wpk + (size_t)(3 + i) * 16384,
                                              wpk + (size_t)(6 + i) * 16384,
                                              nbc + i * D, nbn + i * D, nbe + i * D,
                                              nf_next, N_NODES, 3, 1, act, nullptr);
        cudaEventRecord(ax.evGN[i], s0);

        // G_edge(i) on s1: needs a1e (s0, evS4); ae same-stream
        cudaStreamWaitEvent(s1, ax.evS4[i], 0);
        tc_gemm_k<<<EGB, 256, SM_TOTAL, s1>>>(ef_cur, ae, a1e,
                                              wpk + (size_t)(9 + i) * 16384,
                                              wpk + (size_t)(12 + i) * 16384,
                                              wpk + (size_t)(15 + i) * 16384,
                                              ebc + i * D, ebn + i * D, ebe + i * D,
                                              ef_next, N_EDGES, 3, 1, act, nullptr);
        cudaEventRecord(ax.evGE[i], s1);

        nf_cur = nf_next;
        ef_cur = ef_next;
    }

    // ---- output linears + fused max-pool (concurrent) --------------------------
    tc_gemm_k<<<NGB, 256, SM_TOTAL, s0>>>(nf_cur, nullptr, nullptr,
                                          wpk + (size_t)18 * 16384, nullptr, nullptr,
                                          bno, nullptr, nullptr,
                                          outp + D, N_NODES, 1, 0, 0, pool);
    tc_gemm_k<<<EGB, 256, SM_TOTAL, s1>>>(ef_cur, nullptr, nullptr,
                                          wpk + (size_t)19 * 16384, nullptr, nullptr,
                                          beo, nullptr, nullptr,
                                          outp + D + (size_t)N_NODES * D, N_EDGES,
                                          1, 0, 0, pool + D);
    cudaEventRecord(ax.evJ, s1);
    cudaStreamWaitEvent(s0, ax.evJ, 0);

    pool_combine_k<<<1, 128, 0, s0>>>(pool, outp);
}

// round 14
// speedup vs baseline: 1.2971x; 1.0220x over previous
#include <cuda_runtime.h>
#include <cstdint>
#include <cstddef>

#define N_NODES 50000
#define N_EDGES 800000
#define N_LINE  800000
#define D 128
#define NL 3

// ---------------- scratch (static device globals; no allocations) ----------------
__device__ float g_nf0[(size_t)N_NODES * D];
__device__ float g_nf1[(size_t)N_NODES * D];
__device__ float g_ef0[(size_t)N_EDGES * D];
__device__ float g_ef1[(size_t)N_EDGES * D];
// aggregation buffers: packed bf16 hi/lo rows: [64 u32 hi | 64 u32 lo] per row
__device__ uint32_t g_an [(size_t)N_NODES * D];
__device__ uint32_t g_a1n[(size_t)N_NODES * D];
__device__ uint32_t g_ae [(size_t)N_EDGES * D];
__device__ uint32_t g_a1e0[(size_t)N_EDGES * D];  // ping-pong (cross-stream WAR)
__device__ uint32_t g_a1e1[(size_t)N_EDGES * D];
__device__ unsigned int g_pool[2 * D];
__device__ uint32_t g_wpk[20 * 16384];
// CSR structures (rebuilt every call; indices are static inputs)
__device__ int g_c1o[N_NODES + 1], g_c1c[N_NODES], g_c1l[N_EDGES];  // an:  nf[ei0]->ei1
__device__ int g_c2o[N_NODES + 1], g_c2c[N_NODES], g_c2l[N_EDGES];  // a1n: ef[nei]->nes
__device__ int g_c3o[N_EDGES + 1], g_c3c[N_EDGES], g_c3l[N_LINE];   // ae:  ef[lei0]->lei1
__device__ int g_c4o[N_EDGES + 1], g_c4c[N_EDGES], g_c4l[N_LINE];   // a1e: nf[eni]->ens
__device__ int g_bs[4][1024];

// ============================ CSR build kernels ==================================
__global__ void hist_k(const int* __restrict__ dst, int* __restrict__ cnt, int n)
{
    int i = blockIdx.x * blockDim.x + threadIdx.x;
    if (i < n) atomicAdd(&cnt[dst[i]], 1);
}

#define SCAN_B 1024
__global__ void scan1_k(int* __restrict__ data, int* __restrict__ bsums, int n)
{
    __shared__ int sh[256];
    int t = threadIdx.x;
    int idx = blockIdx.x * SCAN_B + t * 4;
    int v[4], s = 0;
#pragma unroll
    for (int k = 0; k < 4; k++) { v[k] = (idx + k < n) ? data[idx + k] : 0; s += v[k]; }
    sh[t] = s;
    __syncthreads();
#pragma unroll
    for (int o = 1; o < 256; o <<= 1) {
        int x = (t >= o) ? sh[t - o] : 0;
        __syncthreads();
        sh[t] += x;
        __syncthreads();
    }
    int run = sh[t] - s;
#pragma unroll
    for (int k = 0; k < 4; k++) { if (idx + k < n) data[idx + k] = run; run += v[k]; }
    if (t == 255) bsums[blockIdx.x] = sh[255];
}

__global__ void scan2_k(int* __restrict__ bsums, int nb)
{
    __shared__ int sh[1024];
    int t = threadIdx.x;
    int v = (t < nb) ? bsums[t] : 0;
    sh[t] = v;
    __syncthreads();
#pragma unroll
    for (int o = 1; o < 1024; o <<= 1) {
        int x = (t >= o) ? sh[t - o] : 0;
        __syncthreads();
        sh[t] += x;
        __syncthreads();
    }
    if (t < nb) bsums[t] = sh[t] - v;
}

__global__ void scan3_k(int* __restrict__ data, const int* __restrict__ bsums,
                        int* __restrict__ cur, int n)
{
    int i = blockIdx.x * blockDim.x + threadIdx.x;
    if (i < n) {
        int v = data[i] + bsums[i / SCAN_B];
        data[i] = v;
        if (i < n - 1) cur[i] = v;
    }
}

__global__ void fill_k(const int* __restrict__ src, const int* __restrict__ dst,
                       int* __restrict__ cur, int* __restrict__ list, int n)
{
    int i = blockIdx.x * blockDim.x + threadIdx.x;
    if (i < n) {
        int p = atomicAdd(&cur[dst[i]], 1);
        list[p] = src[i];
    }
}

// ============================ bf16 split helpers =================================
__device__ __forceinline__ uint32_t packbf(float hi_el, float lo_el) {
    uint32_t r;
    asm("cvt.rn.bf16x2.f32 %0, %1, %2;" : "=r"(r) : "f"(hi_el), "f"(lo_el));
    return r;
}
__device__ __forceinline__ float bf_lo(uint32_t u) { return __uint_as_float(u << 16); }
__device__ __forceinline__ float bf_hi(uint32_t u) { return __uint_as_float(u & 0xFFFF0000u); }

// ---------------- gather-sum -> packed bf16 hi/lo rows ---------------------------
// One warp per output row. Numerically identical to fp32 gather + in-GEMM split:
// the packbf split just moves from GEMM-read time to gather-write time.
__global__ void gather_pack_k(const float* __restrict__ src, uint32_t* __restrict__ dst,
                              const int* __restrict__ off, const int* __restrict__ lst,
                              int m)
{
    int lane  = threadIdx.x & 31;
    int warp  = (blockIdx.x * blockDim.x + threadIdx.x) >> 5;
    int nwarp = (gridDim.x * blockDim.x) >> 5;
    for (int r = warp; r < m; r += nwarp) {
        int a = off[r], b = off[r + 1];
        float4 acc = make_float4(0.f, 0.f, 0.f, 0.f);
        int k = a;
        for (; k + 1 < b; k += 2) {
            int g0 = lst[k], g1 = lst[k + 1];
            float4 v0 = *((const float4*)(src + (size_t)g0 * D) + lane);
            float4 v1 = *((const float4*)(src + (size_t)g1 * D) + lane);
            acc.x += v0.x + v1.x; acc.y += v0.y + v1.y;
            acc.z += v0.z + v1.z; acc.w += v0.w + v1.w;
        }
        if (k < b) {
            float4 v = *((const float4*)(src + (size_t)lst[k] * D) + lane);
            acc.x += v.x; acc.y += v.y; acc.z += v.z; acc.w += v.w;
        }
        uint32_t h0 = packbf(acc.y, acc.x), h1 = packbf(acc.w, acc.z);
        float r0 = acc.x - bf_lo(h0), r1 = acc.y - bf_hi(h0);
        float r2 = acc.z - bf_lo(h1), r3 = acc.w - bf_hi(h1);
        uint32_t l0 = packbf(r1, r0), l1 = packbf(r3, r2);
        uint32_t* base = dst + (size_t)r * 128;
        *(uint2*)(base + lane * 2)      = make_uint2(h0, h1);
        *(uint2*)(base + 64 + lane * 2) = make_uint2(l0, l1);
    }
}

__device__ __forceinline__ void mma16(float* d, uint32_t a0, uint32_t a1, uint32_t a2,
                                      uint32_t a3, uint32_t b0, uint32_t b1)
{
    asm volatile(
        "mma.sync.aligned.m16n8k16.row.col.f32.bf16.bf16.f32 "
        "{%0,%1,%2,%3}, {%4,%5,%6,%7}, {%8,%9}, {%0,%1,%2,%3};"
        : "+f"(d[0]), "+f"(d[1]), "+f"(d[2]), "+f"(d[3])
        : "r"(a0), "r"(a1), "r"(a2), "r"(a3), "r"(b0), "r"(b1));
}

__device__ __forceinline__ void ldm4(uint32_t* r, uint32_t addr) {
    asm volatile("ldmatrix.sync.aligned.m8n8.x4.shared.b16 {%0,%1,%2,%3}, [%4];"
                 : "=r"(r[0]), "=r"(r[1]), "=r"(r[2]), "=r"(r[3]) : "r"(addr));
}
__device__ __forceinline__ void cp16(uint32_t dst, const void* src) {
    asm volatile("cp.async.ca.shared.global [%0], [%1], 16;" :: "r"(dst), "l"(src));
}
// zero-fill variant: copies srcsz bytes (0 or 16), zero-fills the rest
__device__ __forceinline__ void cp16z(uint32_t dst, const void* src, unsigned srcsz) {
    asm volatile("cp.async.ca.shared.global [%0], [%1], 16, %2;"
                 :: "r"(dst), "l"(src), "r"(srcsz));
}
#define CP_COMMIT() asm volatile("cp.async.commit_group;" ::: "memory")
#define CP_WAIT0()  asm volatile("cp.async.wait_group 0;" ::: "memory")

// ---------------- weight pre-pack (single launch, all 20 matrices) ---------------
__global__ void wprep_all_k(const float* __restrict__ nWc, const float* __restrict__ nWn,
                            const float* __restrict__ nWe, const float* __restrict__ eWc,
                            const float* __restrict__ eWn, const float* __restrict__ eWe,
                            const float* __restrict__ Wno, const float* __restrict__ Weo,
                            uint32_t* __restrict__ out)
{
    int i = blockIdx.x * blockDim.x + threadIdx.x;
    if (i >= 20 * 8192) return;
    int m = i >> 13, r = i & 8191;
    int n = r >> 6, k2 = r & 63;
    const float* srcs[8] = { nWc, nWn, nWe, eWc, eWn, eWe, Wno, Weo };
    int grp = (m < 18) ? (m / 3) : (m - 18 + 6);
    int loc = (m < 18) ? (m % 3) : 0;
    const float* w = srcs[grp] + (size_t)loc * 16384;
    float x0 = w[(2 * k2) * D + n];
    float x1 = w[(2 * k2 + 1) * D + n];
    uint32_t hi = packbf(x1, x0);
    float r0 = x0 - bf_lo(hi);
    float r1 = x1 - bf_hi(hi);
    uint32_t lo = packbf(r1, r0);
    out[(size_t)m * 16384 + n * 64 + k2]        = hi;
    out[(size_t)m * 16384 + 8192 + n * 64 + k2] = lo;
}

// SMEM (dynamic, 82944 B): bias | inv | two 40960B stages | epilogue staging aliased
#define SM_TOTAL 82944
#define STG_BYTES 40960

// ========== bf16x3 tensor-core GEMM, cp.async + ldmatrix 2-stage pipeline ========
// x0: fp32 features (converted in-kernel). px1/px2: PRE-PACKED agg rows (cp.async).
__global__ void __launch_bounds__(256, 2) tc_gemm_k(
    const float* __restrict__ x0,
    const uint32_t* __restrict__ px1, const uint32_t* __restrict__ px2,
    const uint32_t* __restrict__ pk0, const uint32_t* __restrict__ pk1,
    const uint32_t* __restrict__ pk2,
    const float* __restrict__ b0, const float* __restrict__ b1, const float* __restrict__ b2,
    float* __restrict__ out, int M, int nsrc, int donorm, int act,
    unsigned int* __restrict__ pool)
{
    extern __shared__ char smem[];
    float* bias_s = (float*)smem;
    float* inv_s  = (float*)(smem + 512);
    uint32_t stiles = (uint32_t)__cvta_generic_to_shared(smem) + 1024;

    int t = threadIdx.x;
    int lane = t & 31, wid = t >> 5;
    int warpm = wid >> 2, warpn = wid & 3;
    int gid = lane >> 2, tig = lane & 3;
    int row0 = blockIdx.x * 128;

    if (t < D) {
        float bb = b0[t];
        if (nsrc == 3) bb += b1[t] + b2[t];
        bias_s[t] = bb;
    }

    int arow = warpm * 64 + (lane & 7) + ((lane >> 3) & 1) * 8;
    uint32_t aoff = (uint32_t)(arow * 80) + (lane >> 4) * 16;
    int nrow = warpn * 32 + (lane & 7) + (lane >> 4) * 8;
    uint32_t boff = (uint32_t)(nrow * 80) + ((lane >> 3) & 1) * 16;

    int ar = t >> 3;
    int aj = t & 7;

    float acc[4][4][4];
#pragma unroll
    for (int i = 0; i < 4; i++)
#pragma unroll
        for (int j = 0; j < 4; j++)
#pragma unroll
            for (int k = 0; k < 4; k++) acc[i][j][k] = 0.f;

    const uint32_t* ps[3] = { pk0, pk1, pk2 };
    const int nch = nsrc * 4;

    float4 av[4];

    // ---- prologue: chunk 0 (x0, fp32) into stage 0 ------------------------------
    {
#pragma unroll
        for (int h = 0; h < 4; h++) {
            int r = ar + h * 32;
            av[h] = make_float4(0.f, 0.f, 0.f, 0.f);
            if (row0 + r < M)
                av[h] = *(const float4*)(x0 + (size_t)(row0 + r) * D + aj * 4);
        }
        const uint32_t* sH = ps[0];
        const uint32_t* sL = ps[0] + 8192;
        uint32_t dH = stiles + 20480, dL = stiles + 30720;
#pragma unroll
        for (int i = 0; i < 2; i++) {
            int idx = t + i * 256;
            int n = idx >> 2, j4 = idx & 3;
            cp16(dH + n * 80 + j4 * 16, sH + n * 64 + j4 * 4);
            cp16(dL + n * 80 + j4 * 16, sL + n * 64 + j4 * 4);
        }
        CP_COMMIT();
        uint32_t* pH = (uint32_t*)(smem + 1024);
        uint32_t* pL = (uint32_t*)(smem + 1024 + 10240);
#pragma unroll
        for (int h = 0; h < 4; h++) {
            int r = ar + h * 32;
            float4 v = av[h];
            uint32_t h0 = packbf(v.y, v.x), h1 = packbf(v.w, v.z);
            float r0 = v.x - bf_lo(h0), r1 = v.y - bf_hi(h0);
            float r2 = v.z - bf_lo(h1), r3 = v.w - bf_hi(h1);
            *(uint2*)(pH + r * 20 + aj * 2) = make_uint2(h0, h1);
            *(uint2*)(pL + r * 20 + aj * 2) = make_uint2(packbf(r1, r0), packbf(r3, r2));
        }
        CP_WAIT0();
    }
    __syncthreads();

    // ---- main pipelined loop ----------------------------------------------------
    for (int c = 0; c < nch; c++) {
        int s = c & 1;
        int have_next = (c + 1 < nch);
        int c1 = c + 1;

        if (have_next) {
            uint32_t sb = stiles + (s ^ 1) * STG_BYTES;
            if (c1 < 4) {
                // x0 chunk: fp32 prefetch to regs (packed after MMA)
                int kofs = (c1 & 3) * 32;
#pragma unroll
                for (int h = 0; h < 4; h++) {
                    int r = ar + h * 32;
                    av[h] = make_float4(0.f, 0.f, 0.f, 0.f);
                    if (row0 + r < M)
                        av[h] = *(const float4*)(x0 + (size_t)(row0 + r) * D + kofs + aj * 4);
                }
            } else {
                // aggregated chunk: pre-packed rows via cp.async (zero-fill OOB)
                const uint32_t* px = ((c1 >> 2) == 1) ? px1 : px2;
                int k2o = (c1 & 3) * 16;
#pragma unroll
                for (int i = 0; i < 2; i++) {
                    int idx = t + i * 256;            // 512 slots
                    int r = idx >> 2, g = (idx & 3) * 4;
                    int rr = row0 + r;
                    unsigned sz = (rr < M) ? 16u : 0u;
                    const uint32_t* srcb = px + (size_t)rr * 128 + k2o + g;
                    cp16z(sb + r * 80 + g * 4, srcb, sz);
                    cp16z(sb + 10240 + r * 80 + g * 4, srcb + 64, sz);
                }
            }
            // B chunk via cp.async
            const uint32_t* pk = ps[c1 >> 2];
            int k2o = (c1 & 3) * 16;
            const uint32_t* sH = pk + k2o;
            const uint32_t* sL = pk + 8192 + k2o;
            uint32_t dH = sb + 20480, dL = sb + 30720;
#pragma unroll
            for (int i = 0; i < 2; i++) {
                int idx = t + i * 256;
                int n = idx >> 2, j4 = idx & 3;
                cp16(dH + n * 80 + j4 * 16, sH + n * 64 + j4 * 4);
                cp16(dL + n * 80 + j4 * 16, sL + n * 64 + j4 * 4);
            }
            CP_COMMIT();
        }

        // ---- MMA on stage s via ldmatrix ----------------------------------------
        {
            uint32_t bAH = stiles + s * STG_BYTES;
            uint32_t bAL = bAH + 10240;
            uint32_t bBH = bAH + 20480;
            uint32_t bBL = bAH + 30720;
#pragma unroll
            for (int ks = 0; ks < 2; ks++) {
                uint32_t kso = ks * 32;
                uint32_t bh[4][2], bl[4][2], r4[4];
#pragma unroll
                for (int p = 0; p < 2; p++) {
                    ldm4(r4, bBH + boff + p * 1280 + kso);
                    bh[2 * p][0] = r4[0]; bh[2 * p][1] = r4[1];
                    bh[2 * p + 1][0] = r4[2]; bh[2 * p + 1][1] = r4[3];
                    ldm4(r4, bBL + boff + p * 1280 + kso);
                    bl[2 * p][0] = r4[0]; bl[2 * p][1] = r4[1];
                    bl[2 * p + 1][0] = r4[2]; bl[2 * p + 1][1] = r4[3];
                }
#pragma unroll
                for (int mf = 0; mf < 4; mf++) {
                    uint32_t ah[4], al[4];
                    ldm4(ah, bAH + aoff + mf * 1280 + kso);
                    ldm4(al, bAL + aoff + mf * 1280 + kso);
#pragma unroll
                    for (int nf = 0; nf < 4; nf++) {
                        mma16(acc[mf][nf], ah[0], ah[1], ah[2], ah[3], bh[nf][0], bh[nf][1]);
                        mma16(acc[mf][nf], ah[0], ah[1], ah[2], ah[3], bl[nf][0], bl[nf][1]);
                        mma16(acc[mf][nf], al[0], al[1], al[2], al[3], bh[nf][0], bh[nf][1]);
                    }
                }
            }
        }

        if (have_next) {
            if (c1 < 4) {
                uint32_t* pH = (uint32_t*)(smem + 1024 + (s ^ 1) * STG_BYTES);
                uint32_t* pL = pH + 2560;
#pragma unroll
                for (int h = 0; h < 4; h++) {
                    int r = ar + h * 32;
                    float4 v = av[h];
                    uint32_t h0 = packbf(v.y, v.x), h1 = packbf(v.w, v.z);
                    float r0 = v.x - bf_lo(h0), r1 = v.y - bf_hi(h0);
                    float r2 = v.z - bf_lo(h1), r3 = v.w - bf_hi(h1);
                    *(uint2*)(pH + r * 20 + aj * 2) = make_uint2(h0, h1);
                    *(uint2*)(pL + r * 20 + aj * 2) = make_uint2(packbf(r1, r0), packbf(r3, r2));
                }
            }
            CP_WAIT0();
        }
        __syncthreads();
    }

    // ---- epilogue: stage acc + bias into smem (aliases operand tiles) ----------
    float* stg = (float*)(smem + 1024);                // 128 x 132 floats
#pragma unroll
    for (int mf = 0; mf < 4; mf++) {
        int row = warpm * 64 + mf * 16 + gid;
#pragma unroll
        for (int nf = 0; nf < 4; nf++) {
            int col = warpn * 32 + nf * 8 + 2 * tig;
            stg[row * 132 + col]           = acc[mf][nf][0] + bias_s[col];
            stg[row * 132 + col + 1]       = acc[mf][nf][1] + bias_s[col + 1];
            stg[(row + 8) * 132 + col]     = acc[mf][nf][2] + bias_s[col];
            stg[(row + 8) * 132 + col + 1] = acc[mf][nf][3] + bias_s[col + 1];
        }
    }
    __syncthreads();

    if (donorm && t < 128) {
        float ssq = 0.f;
#pragma unroll
        for (int j = 0; j < 32; j++) {
            float4 v = *(float4*)(stg + t * 132 + j * 4);
            ssq += v.x * v.x + v.y * v.y + v.z * v.z + v.w * v.w;
        }
        inv_s[t] = 1.0f / fmaxf(sqrtf(ssq), 1e-12f);
    }
    __syncthreads();

    int sl = t & 31;
    float4 pmax = make_float4(-3.402823466e38f, -3.402823466e38f,
                              -3.402823466e38f, -3.402823466e38f);
#pragma unroll
    for (int h = 0; h < 16; h++) {
        int idx = t + h * 256;
        int row = idx >> 5;
        float4 v = *(float4*)(stg + row * 132 + sl * 4);
        if (donorm) {
            float iv = inv_s[row];
            v.x *= iv; v.y *= iv; v.z *= iv; v.w *= iv;
            if (act) {
                v.x = (v.x >= 0.f) ? v.x : 0.01f * v.x;
                v.y = (v.y >= 0.f) ? v.y : 0.01f * v.y;
                v.z = (v.z >= 0.f) ? v.z : 0.01f * v.z;
                v.w = (v.w >= 0.f) ? v.w : 0.01f * v.w;
            }
        }
        if (row0 + row < M) {
            *(float4*)(out + (size_t)(row0 + row) * D + sl * 4) = v;
            if (pool) {
                pmax.x = fmaxf(pmax.x, v.x); pmax.y = fmaxf(pmax.y, v.y);
                pmax.z = fmaxf(pmax.z, v.z); pmax.w = fmaxf(pmax.w, v.w);
            }
        }
    }
    if (pool) {
        float pv[4] = { pmax.x, pmax.y, pmax.z, pmax.w };
#pragma unroll
        for (int j = 0; j < 4; j++) {
            unsigned u = __float_as_uint(pv[j]);
            unsigned mono = (u & 0x80000000u) ? ~u : (u | 0x80000000u);
            atomicMax(&pool[sl * 4 + j], mono);
        }
    }
}

__global__ void pool_combine_k(unsigned int* __restrict__ pool, float* __restrict__ out)
{
    int t = threadIdx.x;  // 128
    unsigned a = pool[t], bmono = pool[t + D];
    float fa = __uint_as_float((a & 0x80000000u) ? (a & 0x7fffffffu) : ~a);
    float fb = __uint_as_float((bmono & 0x80000000u) ? (bmono & 0x7fffffffu) : ~bmono);
    out[t] = fa + fb;
    pool[t] = 0u;
    pool[t + D] = 0u;
}

// --------- one-time stream/event setup (first, uncaptured, call) -----------------
struct AsyncCtx {
    cudaStream_t s1;
    cudaEvent_t evF, evW, evC, evJ, evGE[NL], evS4[NL];
    AsyncCtx() {
        cudaStreamCreateWithFlags(&s1, cudaStreamNonBlocking);
        cudaEventCreateWithFlags(&evF, cudaEventDisableTiming);
        cudaEventCreateWithFlags(&evW, cudaEventDisableTiming);
        cudaEventCreateWithFlags(&evC, cudaEventDisableTiming);
        cudaEventCreateWithFlags(&evJ, cudaEventDisableTiming);
        for (int i = 0; i < NL; i++) {
            cudaEventCreateWithFlags(&evGE[i], cudaEventDisableTiming);
            cudaEventCreateWithFlags(&evS4[i], cudaEventDisableTiming);
        }
    }
};

static void build_csr(const int* src, const int* dst, int cnt_n,
                      int* off, int* cur, int* list, int m, int* bs, cudaStream_t st)
{
    int nscan = m + 1;
    int nb = (nscan + SCAN_B - 1) / SCAN_B;
    cudaMemsetAsync(off, 0, (size_t)nscan * sizeof(int), st);
    hist_k<<<(cnt_n + 255) / 256, 256, 0, st>>>(dst, off, cnt_n);
    scan1_k<<<nb, 256, 0, st>>>(off, bs, nscan);
    scan2_k<<<1, 1024, 0, st>>>(bs, nb);
    scan3_k<<<(nscan + 255) / 256, 256, 0, st>>>(off, bs, cur, nscan);
    fill_k<<<(cnt_n + 255) / 256, 256, 0, st>>>(src, dst, cur, list, cnt_n);
}

// ---------------------------------- launch ---------------------------------------
extern "C" void kernel_launch(void* const* d_in, const int* in_sizes, int n_in,
                              void* d_out, int out_size)
{
    static AsyncCtx ax;

    const float* nf_in = (const float*)d_in[0];
    const float* ef_in = (const float*)d_in[1];
    const float* nWc = (const float*)d_in[2];
    const float* nbc = (const float*)d_in[3];
    const float* nWn = (const float*)d_in[4];
    const float* nbn = (const float*)d_in[5];
    const float* nWe = (const float*)d_in[6];
    const float* nbe = (const float*)d_in[7];
    const float* eWc = (const float*)d_in[8];
    const float* ebc = (const float*)d_in[9];
    const float* eWn = (const float*)d_in[10];
    const float* ebn = (const float*)d_in[11];
    const float* eWe = (const float*)d_in[12];
    const float* ebe = (const float*)d_in[13];
    const float* Wno = (const float*)d_in[14];
    const float* bno = (const float*)d_in[15];
    const float* Weo = (const float*)d_in[16];
    const float* beo = (const float*)d_in[17];
    const int* ei  = (const int*)d_in[18];   // [2, E]
    const int* lei = (const int*)d_in[19];   // [2, L]
    const int* nei = (const int*)d_in[20];   // [E]
    const int* nes = (const int*)d_in[21];   // [E]
    const int* eni = (const int*)d_in[22];   // [L]
    const int* ens = (const int*)d_in[23];   // [L]
    float* outp = (float*)d_out;             // [pooled(128) | tn(N*128) | te(E*128)]

    cudaFuncSetAttribute(tc_gemm_k, cudaFuncAttributeMaxDynamicSharedMemorySize, SM_TOTAL);

    float *nf0, *nf1, *ef0, *ef1;
    uint32_t *an, *a1n, *ae, *a1eP[2];
    unsigned int* pool;
    uint32_t* wpk;
    int *c1o, *c1c, *c1l, *c2o, *c2c, *c2l, *c3o, *c3c, *c3l, *c4o, *c4c, *c4l, *bs;
    cudaGetSymbolAddress((void**)&nf0, g_nf0);
    cudaGetSymbolAddress((void**)&nf1, g_nf1);
    cudaGetSymbolAddress((void**)&ef0, g_ef0);
    cudaGetSymbolAddress((void**)&ef1, g_ef1);
    cudaGetSymbolAddress((void**)&an,  g_an);
    cudaGetSymbolAddress((void**)&a1n, g_a1n);
    cudaGetSymbolAddress((void**)&ae,  g_ae);
    cudaGetSymbolAddress((void**)&a1eP[0], g_a1e0);
    cudaGetSymbolAddress((void**)&a1eP[1], g_a1e1);
    cudaGetSymbolAddress((void**)&pool, g_pool);
    cudaGetSymbolAddress((void**)&wpk, g_wpk);
    cudaGetSymbolAddress((void**)&c1o, g_c1o); cudaGetSymbolAddress((void**)&c1c, g_c1c);
    cudaGetSymbolAddress((void**)&c1l, g_c1l);
    cudaGetSymbolAddress((void**)&c2o, g_c2o); cudaGetSymbolAddress((void**)&c2c, g_c2c);
    cudaGetSymbolAddress((void**)&c2l, g_c2l);
    cudaGetSymbolAddress((void**)&c3o, g_c3o); cudaGetSymbolAddress((void**)&c3c, g_c3c);
    cudaGetSymbolAddress((void**)&c3l, g_c3l);
    cudaGetSymbolAddress((void**)&c4o, g_c4o); cudaGetSymbolAddress((void**)&c4c, g_c4c);
    cudaGetSymbolAddress((void**)&c4l, g_c4l);
    cudaGetSymbolAddress((void**)&bs, g_bs);

    cudaStream_t s0 = 0, s1 = ax.s1;

    // fork s1
    cudaEventRecord(ax.evF, s0);
    cudaStreamWaitEvent(s1, ax.evF, 0);

    // s0: weights + node CSRs.  s1: edge CSRs (concurrent).
    wprep_all_k<<<(20 * 8192 + 255) / 256, 256, 0, s0>>>(nWc, nWn, nWe, eWc, eWn, eWe,
                                                         Wno, Weo, wpk);
    cudaEventRecord(ax.evW, s0);
    build_csr(ei,  ei + N_EDGES, N_EDGES, c1o, c1c, c1l, N_NODES, bs,        s0);
    build_csr(nei, nes,          N_EDGES, c2o, c2c, c2l, N_NODES, bs + 1024, s0);
    build_csr(lei, lei + N_LINE, N_LINE,  c3o, c3c, c3l, N_EDGES, bs + 2048, s1);
    build_csr(eni, ens,          N_LINE,  c4o, c4c, c4l, N_EDGES, bs + 3072, s1);
    cudaEventRecord(ax.evC, s1);          // s1 CSR builds complete (c3, c4)
    cudaStreamWaitEvent(s1, ax.evW, 0);   // G_edge(0) needs packed weights
    cudaStreamWaitEvent(s0, ax.evC, 0);   // s0's a1e gather reads c4

    float* nf_bufs[2] = { nf0, nf1 };
    float* ef_bufs[2] = { ef0, ef1 };
    const float* nf_cur = nf_in;
    const float* ef_cur = ef_in;

    const int EGW = 25000;    // gather grid (edge-sized outputs)
    const int NGW = 6250;     // gather grid (node-sized outputs)
    const int NGB = (N_NODES + 127) / 128;   // 391
    const int EGB = (N_EDGES + 127) / 128;   // 6250

    for (int i = 0; i < NL; i++) {
        float* nf_next = nf_bufs[i & 1];
        float* ef_next = ef_bufs[i & 1];
        uint32_t* a1e = a1eP[i & 1];
        int act = (i < NL - 1);

        // ---- s0: nf-sourced gathers (run during previous G_edge) ---------------
        // WAR on a1e[p]: previous reader is G_edge(i-2); s0 waited evGE[i-2] in
        // layer i-1, ordering these writes. nf_cur is s0-local.
        gather_pack_k<<<NGW, 256, 0, s0>>>(nf_cur, an,  c1o, c1l, N_NODES);
        gather_pack_k<<<EGW, 256, 0, s0>>>(nf_cur, a1e, c4o, c4l, N_EDGES);
        cudaEventRecord(ax.evS4[i], s0);

        // ---- ef-sourced gathers (need ef_cur = G_edge(i-1) output) -------------
        if (i > 0) cudaStreamWaitEvent(s0, ax.evGE[i - 1], 0);
        gather_pack_k<<<EGW, 256, 0, s0>>>(ef_cur, a1n, c2o, c2l, N_NODES);
        gather_pack_k<<<EGW, 256, 0, s1>>>(ef_cur, ae,  c3o, c3l, N_EDGES);

        // G_node(i) on s0
        tc_gemm_k<<<NGB, 256, SM_TOTAL, s0>>>(nf_cur, an, a1n,
                                              wpk + (size_t)(0 + i) * 16384,
                                              wpk + (size_t)(3 + i) * 16384,
                                              wpk + (size_t)(6 + i) * 16384,
                                              nbc + i * D, nbn + i * D, nbe + i * D,
                                              nf_next, N_NODES, 3, 1, act, nullptr);

        // G_edge(i) on s1: needs a1e (s0, evS4); ae same-stream
        cudaStreamWaitEvent(s1, ax.evS4[i], 0);
        tc_gemm_k<<<EGB, 256, SM_TOTAL, s1>>>(ef_cur, ae, a1e,
                                              wpk + (size_t)(9 + i) * 16384,
                                              wpk + (size_t)(12 + i) * 16384,
                                              wpk + (size_t)(15 + i) * 16384,
                                              ebc + i * D, ebn + i * D, ebe + i * D,
                                              ef_next, N_EDGES, 3, 1, act, nullptr);
        cudaEventRecord(ax.evGE[i], s1);

        nf_cur = nf_next;
        ef_cur = ef_next;
    }

    // ---- output linears + fused max-pool (concurrent) --------------------------
    tc_gemm_k<<<NGB, 256, SM_TOTAL, s0>>>(nf_cur, nullptr, nullptr,
                                          wpk + (size_t)18 * 16384, nullptr, nullptr,
                                          bno, nullptr, nullptr,
                                          outp + D, N_NODES, 1, 0, 0, pool);
    tc_gemm_k<<<EGB, 256, SM_TOTAL, s1>>>(ef_cur, nullptr, nullptr,
                                          wpk + (size_t)19 * 16384, nullptr, nullptr,
                                          beo, nullptr, nullptr,
                                          outp + D + (size_t)N_NODES * D, N_EDGES,
                                          1, 0, 0, pool + D);
    cudaEventRecord(ax.evJ, s1);
    cudaStreamWaitEvent(s0, ax.evJ, 0);

    pool_combine_k<<<1, 128, 0, s0>>>(pool, outp);
}